// round 1
// baseline (speedup 1.0000x reference)
#include <cuda_runtime.h>

// Problem constants
#define NB      768          // N*C
#define HH      62
#define WW      64
#define HP      64           // padded H
#define KCODE   256
#define NPAIR   128
#define CHUNKS_PER_B 1024    // W * Hp / D
#define M_TOTAL (NB * CHUNKS_PER_B)          // 786432
#define QL_ELEMS (NB * HH * WW)              // 3047424
#define OFF_MSE   QL_ELEMS                   // 3047424
#define OFF_INDS  (QL_ELEMS + 1)             // 3047425
#define OFF_RATE  (OFF_INDS + M_TOTAL)       // 3833857
#define OFF_PRIOR (OFF_RATE + 1)
#define OFF_PARAM (OFF_RATE + 2)
#define MSE_COUNT 3145728.0f                 // NB * 1024 * 4

#define NEG_INV_LN2 (-1.4426950408889634f)   // log2_pmf = log_pmf * NEG_INV_LN2
#define INV_LMBDA   100.0f

typedef unsigned long long u64;

// Deterministic per-block partials (device globals: no allocation in kernel_launch)
__device__ float g_pmse[NB];
__device__ float g_prate[NB];

__device__ __forceinline__ u64 pack2(float lo, float hi) {
    u64 r; asm("mov.b64 %0,{%1,%2};" : "=l"(r) : "f"(lo), "f"(hi)); return r;
}
__device__ __forceinline__ void unpack2(u64 v, float& lo, float& hi) {
    asm("mov.b64 {%0,%1},%2;" : "=f"(lo), "=f"(hi) : "l"(v));
}
// packed dual-fp32 FMA (Blackwell f32x2 pipe; 2 MACs per issue slot)
__device__ __forceinline__ u64 fma2(u64 a, u64 b, u64 c) {
    u64 d; asm("fma.rn.f32x2 %0,%1,%2,%3;" : "=l"(d) : "l"(a), "l"(b), "l"(c)); return d;
}

__global__ __launch_bounds__(512)
void vq_main(const float* __restrict__ lat,
             const float* __restrict__ cb,
             const float* __restrict__ lpmf,
             float* __restrict__ out)
{
    // Packed codebook: per pair p -> {-2*c[2p][d], -2*c[2p+1][d]} and bias pair
    __shared__ u64   s_nc[NPAIR][4];
    __shared__ u64   s_bias[NPAIR];
    __shared__ float4 s_cw[KCODE];
    __shared__ float  s_l2p[KCODE];
    __shared__ float  s_ind[CHUNKS_PER_B];
    __shared__ float  s_rm[16];
    __shared__ float  s_rr[16];

    const int tid = threadIdx.x;
    const int b   = blockIdx.x;

    // ---- per-block codebook prep (cheap: codebook is tiny, stays in L2) ----
    if (tid < KCODE) {
        float4 ck = *(const float4*)(cb + tid * 4);
        s_cw[tid]  = ck;
        s_l2p[tid] = lpmf[tid] * NEG_INV_LN2;
    }
    if (tid < NPAIR) {
        const int p = tid;
        float4 c0 = *(const float4*)(cb + (2 * p) * 4);
        float4 c1 = *(const float4*)(cb + (2 * p + 1) * 4);
        s_nc[p][0] = pack2(-2.f * c0.x, -2.f * c1.x);
        s_nc[p][1] = pack2(-2.f * c0.y, -2.f * c1.y);
        s_nc[p][2] = pack2(-2.f * c0.z, -2.f * c1.z);
        s_nc[p][3] = pack2(-2.f * c0.w, -2.f * c1.w);
        float b0 = c0.x*c0.x + c0.y*c0.y + c0.z*c0.z + c0.w*c0.w
                 + lpmf[2*p]     * NEG_INV_LN2 * INV_LMBDA;
        float b1 = c1.x*c1.x + c1.y*c1.y + c1.z*c1.z + c1.w*c1.w
                 + lpmf[2*p + 1] * NEG_INV_LN2 * INV_LMBDA;
        s_bias[p] = pack2(b0, b1);
    }
    __syncthreads();

    // ---- thread -> 2 chunks of this b: (cA, w) and (cA+8, w) ----
    // Lanes sweep w => all latents loads / ql stores are 128B-coalesced.
    const int w  = tid & 63;
    const int cA = tid >> 6;      // 0..7
    const int cB = cA + 8;        // 8..15 (cB==15 holds padded rows 62,63 -> 60,61)

    const float* base = lat + (size_t)b * (HH * WW) + w;

    float xa0 = base[(4 * cA + 0) * WW];
    float xa1 = base[(4 * cA + 1) * WW];
    float xa2 = base[(4 * cA + 2) * WW];
    float xa3 = base[(4 * cA + 3) * WW];

    int hb0 = 4 * cB + 0, hb1 = 4 * cB + 1, hb2 = 4 * cB + 2, hb3 = 4 * cB + 3;
    int sb0 = (hb0 < HH) ? hb0 : hb0 - 2;
    int sb1 = (hb1 < HH) ? hb1 : hb1 - 2;
    int sb2 = (hb2 < HH) ? hb2 : hb2 - 2;
    int sb3 = (hb3 < HH) ? hb3 : hb3 - 2;
    float xb0 = base[sb0 * WW];
    float xb1 = base[sb1 * WW];
    float xb2 = base[sb2 * WW];
    float xb3 = base[sb3 * WW];

    u64 xa_p0 = pack2(xa0, xa0), xa_p1 = pack2(xa1, xa1);
    u64 xa_p2 = pack2(xa2, xa2), xa_p3 = pack2(xa3, xa3);
    u64 xb_p0 = pack2(xb0, xb0), xb_p1 = pack2(xb1, xb1);
    u64 xb_p2 = pack2(xb2, xb2), xb_p3 = pack2(xb3, xb3);

    float bestA = 3.4e38f, bestB = 3.4e38f;
    int   biA = 0, biB = 0;

    // score_k = (||c_k||^2 + log2_pmf_k/lambda) - 2 * <x, c_k>
    // (||x||^2 dropped: constant per row, doesn't change argmin)
    #pragma unroll 8
    for (int p = 0; p < NPAIR; ++p) {
        u64 n0 = s_nc[p][0], n1 = s_nc[p][1], n2 = s_nc[p][2], n3 = s_nc[p][3];
        u64 bias = s_bias[p];

        u64 accA = bias;
        accA = fma2(xa_p0, n0, accA);
        accA = fma2(xa_p1, n1, accA);
        accA = fma2(xa_p2, n2, accA);
        accA = fma2(xa_p3, n3, accA);

        u64 accB = bias;
        accB = fma2(xb_p0, n0, accB);
        accB = fma2(xb_p1, n1, accB);
        accB = fma2(xb_p2, n2, accB);
        accB = fma2(xb_p3, n3, accB);

        float a0, a1, b0, b1;
        unpack2(accA, a0, a1);
        unpack2(accB, b0, b1);
        // strict < keeps "first index wins" (k ascending), matching jnp.argmin
        if (a0 < bestA) { bestA = a0; biA = 2 * p; }
        if (a1 < bestA) { bestA = a1; biA = 2 * p + 1; }
        if (b0 < bestB) { bestB = b0; biB = 2 * p; }
        if (b1 < bestB) { bestB = b1; biB = 2 * p + 1; }
    }

    // ---- gather chosen codewords, write ql (cropped), accumulate losses ----
    float4 qa = s_cw[biA];
    float4 qb = s_cw[biB];

    float* oql = out + (size_t)b * (HH * WW) + w;
    oql[(4 * cA + 0) * WW] = qa.x;
    oql[(4 * cA + 1) * WW] = qa.y;
    oql[(4 * cA + 2) * WW] = qa.z;
    oql[(4 * cA + 3) * WW] = qa.w;
    // chunk B: only rows < 62 exist in the output (padded rows are cropped)
    if (hb0 < HH) oql[hb0 * WW] = qb.x;
    if (hb1 < HH) oql[hb1 * WW] = qb.y;
    if (hb2 < HH) oql[hb2 * WW] = qb.z;
    if (hb3 < HH) oql[hb3 * WW] = qb.w;

    float da0 = qa.x - xa0, da1 = qa.y - xa1, da2 = qa.z - xa2, da3 = qa.w - xa3;
    float db0 = qb.x - xb0, db1 = qb.y - xb1, db2 = qb.z - xb2, db3 = qb.w - xb3;
    float lm = da0*da0 + da1*da1 + da2*da2 + da3*da3
             + db0*db0 + db1*db1 + db2*db2 + db3*db3;
    float lr = s_l2p[biA] + s_l2p[biB];

    // inds in flat order m = b*1024 + w*16 + c  (SMEM transpose -> coalesced store)
    s_ind[w * 16 + cA] = (float)biA;
    s_ind[w * 16 + cB] = (float)biB;

    // ---- deterministic block reduction ----
    #pragma unroll
    for (int o = 16; o > 0; o >>= 1) {
        lm += __shfl_down_sync(0xFFFFFFFFu, lm, o);
        lr += __shfl_down_sync(0xFFFFFFFFu, lr, o);
    }
    if ((tid & 31) == 0) { s_rm[tid >> 5] = lm; s_rr[tid >> 5] = lr; }
    __syncthreads();

    // coalesced inds writeout
    float* oind = out + OFF_INDS + (size_t)b * CHUNKS_PER_B;
    oind[tid]       = s_ind[tid];
    oind[tid + 512] = s_ind[tid + 512];

    if (tid == 0) {
        float sm_ = 0.f, sr_ = 0.f;
        #pragma unroll
        for (int i = 0; i < 16; ++i) { sm_ += s_rm[i]; sr_ += s_rr[i]; }
        g_pmse[b]  = sm_;
        g_prate[b] = sr_;
    }
}

__global__ __launch_bounds__(256)
void vq_final(float* __restrict__ out)
{
    __shared__ float sm[256];
    __shared__ float sr[256];
    const int t = threadIdx.x;
    float a = 0.f, r = 0.f;
    #pragma unroll
    for (int i = 0; i < 3; ++i) {       // 768 = 256*3, fixed order -> deterministic
        a += g_pmse[t + i * 256];
        r += g_prate[t + i * 256];
    }
    sm[t] = a; sr[t] = r;
    __syncthreads();
    #pragma unroll
    for (int s = 128; s > 0; s >>= 1) {
        if (t < s) { sm[t] += sm[t + s]; sr[t] += sr[t + s]; }
        __syncthreads();
    }
    if (t == 0) {
        out[OFF_MSE]   = sm[0] * (1.0f / MSE_COUNT);
        out[OFF_RATE]  = sr[0];
        out[OFF_PRIOR] = 0.f;
        out[OFF_PARAM] = 0.f;
    }
}

extern "C" void kernel_launch(void* const* d_in, const int* in_sizes, int n_in,
                              void* d_out, int out_size)
{
    const float* lat  = (const float*)d_in[0];   // latents  (4,192,62,64)
    const float* cb   = (const float*)d_in[1];   // codebook (256,4)
    const float* lpmf = (const float*)d_in[2];   // log_pmf  (256,)
    float* out = (float*)d_out;

    vq_main<<<NB, 512>>>(lat, cb, lpmf, out);
    vq_final<<<1, 256>>>(out);
}

// round 2
// speedup vs baseline: 1.0085x; 1.0085x over previous
#include <cuda_runtime.h>

// Problem constants
#define NB      768          // N*C
#define HH      62
#define WW      64
#define KCODE   256
#define NPAIR   128
#define CHUNKS_PER_B 1024    // W * Hp / D
#define M_TOTAL (NB * CHUNKS_PER_B)          // 786432
#define QL_ELEMS (NB * HH * WW)              // 3047424
#define OFF_MSE   QL_ELEMS
#define OFF_INDS  (QL_ELEMS + 1)
#define OFF_RATE  (OFF_INDS + M_TOTAL)
#define OFF_PRIOR (OFF_RATE + 1)
#define OFF_PARAM (OFF_RATE + 2)
#define MSE_COUNT 3145728.0f                 // NB * 1024 * 4

#define NEG_INV_LN2 (-1.4426950408889634f)
#define INV_LMBDA   100.0f

typedef unsigned long long u64;

// Deterministic per-block partials + completion counter (device globals: no allocs)
__device__ float g_pmse[NB];
__device__ float g_prate[NB];
__device__ int   g_count;        // zero-initialized; last block resets it -> replayable

__device__ __forceinline__ u64 pack2(float lo, float hi) {
    u64 r; asm("mov.b64 %0,{%1,%2};" : "=l"(r) : "f"(lo), "f"(hi)); return r;
}
__device__ __forceinline__ void unpack2(u64 v, float& lo, float& hi) {
    asm("mov.b64 {%0,%1},%2;" : "=f"(lo), "=f"(hi) : "l"(v));
}
// packed dual-fp32 FMA (Blackwell f32x2 pipe; 2 MACs per issue slot)
__device__ __forceinline__ u64 fma2(u64 a, u64 b, u64 c) {
    u64 d; asm("fma.rn.f32x2 %0,%1,%2,%3;" : "=l"(d) : "l"(a), "l"(b), "l"(c)); return d;
}

__global__ __launch_bounds__(256, 2)
void vq_main(const float* __restrict__ lat,
             const float* __restrict__ cb,
             const float* __restrict__ lpmf,
             float* __restrict__ out)
{
    // Packed codebook: pair p -> {-2*c[2p][d], -2*c[2p+1][d]} split for LDS.128 loads
    __shared__ ulonglong2 s_n01[NPAIR];   // {n_d0, n_d1}
    __shared__ ulonglong2 s_n23[NPAIR];   // {n_d2, n_d3}
    __shared__ u64        s_bias[NPAIR];
    __shared__ float4     s_cw[KCODE];
    __shared__ float      s_l2p[KCODE];
    __shared__ float      s_ind[CHUNKS_PER_B];
    __shared__ float      s_rm[8];
    __shared__ float      s_rr[8];
    __shared__ int        s_last;

    const int tid = threadIdx.x;
    const int b   = blockIdx.x;

    // ---- codebook prep (tiny; stays hot in L2 across blocks) ----
    {
        float4 ck = *(const float4*)(cb + tid * 4);
        s_cw[tid]  = ck;
        s_l2p[tid] = lpmf[tid] * NEG_INV_LN2;
    }
    if (tid < NPAIR) {
        const int p = tid;
        float4 c0 = *(const float4*)(cb + (2 * p) * 4);
        float4 c1 = *(const float4*)(cb + (2 * p + 1) * 4);
        ulonglong2 a, bq;
        a.x  = pack2(-2.f * c0.x, -2.f * c1.x);
        a.y  = pack2(-2.f * c0.y, -2.f * c1.y);
        bq.x = pack2(-2.f * c0.z, -2.f * c1.z);
        bq.y = pack2(-2.f * c0.w, -2.f * c1.w);
        s_n01[p] = a;
        s_n23[p] = bq;
        float b0 = c0.x*c0.x + c0.y*c0.y + c0.z*c0.z + c0.w*c0.w
                 + lpmf[2*p]     * NEG_INV_LN2 * INV_LMBDA;
        float b1 = c1.x*c1.x + c1.y*c1.y + c1.z*c1.z + c1.w*c1.w
                 + lpmf[2*p + 1] * NEG_INV_LN2 * INV_LMBDA;
        s_bias[p] = pack2(b0, b1);
    }
    __syncthreads();

    // ---- thread -> 4 chunks (c, w0..w0+3) of block b ----
    const int w0 = (tid & 15) * 4;     // 16 w-groups of 4
    const int c  = tid >> 4;           // 0..15 chunk row-group

    const int h0 = 4 * c, h1 = h0 + 1, h2 = h0 + 2, h3 = h0 + 3;
    const int s2 = (h2 < HH) ? h2 : h2 - 2;   // c==15: 62 -> 60
    const int s3 = (h3 < HH) ? h3 : h3 - 2;   // c==15: 63 -> 61

    const float* base = lat + (size_t)b * (HH * WW) + w0;
    float4 v0 = *(const float4*)(base + h0 * WW);
    float4 v1 = *(const float4*)(base + h1 * WW);
    float4 v2 = *(const float4*)(base + s2 * WW);
    float4 v3 = *(const float4*)(base + s3 * WW);

    const float* f0 = (const float*)&v0;
    const float* f1 = (const float*)&v1;
    const float* f2 = (const float*)&v2;
    const float* f3 = (const float*)&v3;

    // chunk j (w = w0+j) has elements (f0[j], f1[j], f2[j], f3[j]); pack duplicated
    u64 xq0[4], xq1[4], xq2[4], xq3[4];
    #pragma unroll
    for (int j = 0; j < 4; ++j) {
        xq0[j] = pack2(f0[j], f0[j]);
        xq1[j] = pack2(f1[j], f1[j]);
        xq2[j] = pack2(f2[j], f2[j]);
        xq3[j] = pack2(f3[j], f3[j]);
    }

    float best0 = 3.4e38f, best1 = 3.4e38f, best2 = 3.4e38f, best3 = 3.4e38f;
    int   bi0 = 0, bi1 = 0, bi2 = 0, bi3 = 0;

    // score_k = (||c_k||^2 + log2_pmf_k/lambda) - 2 * <x, c_k>
    // (same accumulation order as the validated R1 kernel)
    #pragma unroll 4
    for (int p = 0; p < NPAIR; ++p) {
        ulonglong2 n01 = s_n01[p];
        ulonglong2 n23 = s_n23[p];
        u64 bias = s_bias[p];

        u64 a0 = fma2(xq0[0], n01.x, bias);
        u64 a1 = fma2(xq0[1], n01.x, bias);
        u64 a2 = fma2(xq0[2], n01.x, bias);
        u64 a3 = fma2(xq0[3], n01.x, bias);
        a0 = fma2(xq1[0], n01.y, a0);
        a1 = fma2(xq1[1], n01.y, a1);
        a2 = fma2(xq1[2], n01.y, a2);
        a3 = fma2(xq1[3], n01.y, a3);
        a0 = fma2(xq2[0], n23.x, a0);
        a1 = fma2(xq2[1], n23.x, a1);
        a2 = fma2(xq2[2], n23.x, a2);
        a3 = fma2(xq3[3], n23.x, a3);  // placeholder to keep symmetry (fixed below)
        a3 = fma2(xq2[3], n23.x, fma2(xq1[3], n01.y, fma2(xq0[3], n01.x, bias)));
        a3 = fma2(xq3[3], n23.y, a3);
        a0 = fma2(xq3[0], n23.y, a0);
        a1 = fma2(xq3[1], n23.y, a1);
        a2 = fma2(xq3[2], n23.y, a2);

        float sa, sb;
        unpack2(a0, sa, sb);
        if (sa < best0) { best0 = sa; bi0 = 2 * p; }
        if (sb < best0) { best0 = sb; bi0 = 2 * p + 1; }
        unpack2(a1, sa, sb);
        if (sa < best1) { best1 = sa; bi1 = 2 * p; }
        if (sb < best1) { best1 = sb; bi1 = 2 * p + 1; }
        unpack2(a2, sa, sb);
        if (sa < best2) { best2 = sa; bi2 = 2 * p; }
        if (sb < best2) { best2 = sb; bi2 = 2 * p + 1; }
        unpack2(a3, sa, sb);
        if (sa < best3) { best3 = sa; bi3 = 2 * p; }
        if (sb < best3) { best3 = sb; bi3 = 2 * p + 1; }
    }

    // ---- gather chosen codewords ----
    float4 q0 = s_cw[bi0];
    float4 q1 = s_cw[bi1];
    float4 q2 = s_cw[bi2];
    float4 q3 = s_cw[bi3];

    // ql writes: row d at (h_d, w0..w0+3) = (q0[d], q1[d], q2[d], q3[d]) -> STG.128
    float* oql = out + (size_t)b * (HH * WW) + w0;
    {
        float4 r0 = make_float4(q0.x, q1.x, q2.x, q3.x);
        float4 r1 = make_float4(q0.y, q1.y, q2.y, q3.y);
        *(float4*)(oql + h0 * WW) = r0;
        *(float4*)(oql + h1 * WW) = r1;
        if (h2 < HH) {
            float4 r2 = make_float4(q0.z, q1.z, q2.z, q3.z);
            *(float4*)(oql + h2 * WW) = r2;
        }
        if (h3 < HH) {
            float4 r3 = make_float4(q0.w, q1.w, q2.w, q3.w);
            *(float4*)(oql + h3 * WW) = r3;
        }
    }

    // mse / rate partials (all 16 elements count, incl. padded duplicates)
    float lm, lr;
    {
        float d00 = q0.x - f0[0], d01 = q0.y - f1[0], d02 = q0.z - f2[0], d03 = q0.w - f3[0];
        float d10 = q1.x - f0[1], d11 = q1.y - f1[1], d12 = q1.z - f2[1], d13 = q1.w - f3[1];
        float d20 = q2.x - f0[2], d21 = q2.y - f1[2], d22 = q2.z - f2[2], d23 = q2.w - f3[2];
        float d30 = q3.x - f0[3], d31 = q3.y - f1[3], d32 = q3.z - f2[3], d33 = q3.w - f3[3];
        lm = d00*d00 + d01*d01 + d02*d02 + d03*d03
           + d10*d10 + d11*d11 + d12*d12 + d13*d13
           + d20*d20 + d21*d21 + d22*d22 + d23*d23
           + d30*d30 + d31*d31 + d32*d32 + d33*d33;
        lr = s_l2p[bi0] + s_l2p[bi1] + s_l2p[bi2] + s_l2p[bi3];
    }

    // inds: flat order m = b*1024 + w*16 + c  (SMEM transpose -> coalesced stores)
    s_ind[(w0 + 0) * 16 + c] = (float)bi0;
    s_ind[(w0 + 1) * 16 + c] = (float)bi1;
    s_ind[(w0 + 2) * 16 + c] = (float)bi2;
    s_ind[(w0 + 3) * 16 + c] = (float)bi3;

    // ---- deterministic block reduction ----
    #pragma unroll
    for (int o = 16; o > 0; o >>= 1) {
        lm += __shfl_down_sync(0xFFFFFFFFu, lm, o);
        lr += __shfl_down_sync(0xFFFFFFFFu, lr, o);
    }
    if ((tid & 31) == 0) { s_rm[tid >> 5] = lm; s_rr[tid >> 5] = lr; }
    __syncthreads();

    // coalesced inds writeout
    float* oind = out + OFF_INDS + (size_t)b * CHUNKS_PER_B;
    oind[tid]       = s_ind[tid];
    oind[tid + 256] = s_ind[tid + 256];
    oind[tid + 512] = s_ind[tid + 512];
    oind[tid + 768] = s_ind[tid + 768];

    if (tid == 0) {
        float sm_ = 0.f, sr_ = 0.f;
        #pragma unroll
        for (int i = 0; i < 8; ++i) { sm_ += s_rm[i]; sr_ += s_rr[i]; }
        g_pmse[b]  = sm_;
        g_prate[b] = sr_;
        __threadfence();
        int v = atomicAdd(&g_count, 1);
        s_last = (v == NB - 1);
    }
    __syncthreads();

    // ---- fused finalize: last block reduces the 768 partials (fixed order) ----
    if (s_last) {
        __threadfence();   // acquire: make all blocks' partials visible
        float a = g_pmse[tid] + g_pmse[tid + 256] + g_pmse[tid + 512];
        float r = g_prate[tid] + g_prate[tid + 256] + g_prate[tid + 512];
        s_ind[tid]       = a;          // reuse smem
        s_ind[tid + 256] = r;
        __syncthreads();
        #pragma unroll
        for (int s = 128; s > 0; s >>= 1) {
            if (tid < s) {
                s_ind[tid]       += s_ind[tid + s];
                s_ind[256 + tid] += s_ind[256 + tid + s];
            }
            __syncthreads();
        }
        if (tid == 0) {
            out[OFF_MSE]   = s_ind[0] * (1.0f / MSE_COUNT);
            out[OFF_RATE]  = s_ind[256];
            out[OFF_PRIOR] = 0.f;
            out[OFF_PARAM] = 0.f;
            g_count = 0;   // reset for next graph replay
        }
    }
}

extern "C" void kernel_launch(void* const* d_in, const int* in_sizes, int n_in,
                              void* d_out, int out_size)
{
    const float* lat  = (const float*)d_in[0];   // latents  (4,192,62,64)
    const float* cb   = (const float*)d_in[1];   // codebook (256,4)
    const float* lpmf = (const float*)d_in[2];   // log_pmf  (256,)
    float* out = (float*)d_out;

    vq_main<<<NB, 256>>>(lat, cb, lpmf, out);
}

// round 5
// speedup vs baseline: 1.4335x; 1.4214x over previous
#include <cuda_runtime.h>

// Problem constants
#define NB      768          // N*C
#define HH      62
#define WW      64
#define KCODE   256
#define NPAIR   128
#define CHUNKS_PER_B 1024    // W * Hp / D
#define M_TOTAL (NB * CHUNKS_PER_B)          // 786432
#define QL_ELEMS (NB * HH * WW)              // 3047424
#define OFF_MSE   QL_ELEMS
#define OFF_INDS  (QL_ELEMS + 1)
#define OFF_RATE  (OFF_INDS + M_TOTAL)
#define OFF_PRIOR (OFF_RATE + 1)
#define OFF_PARAM (OFF_RATE + 2)
#define MSE_COUNT 3145728.0f                 // NB * 1024 * 4

#define NEG_INV_LN2 (-1.4426950408889634f)
#define INV_LMBDA   100.0f

typedef unsigned long long u64;

// Deterministic per-block partials + completion counter (device globals: no allocs)
__device__ float g_pmse[NB];
__device__ float g_prate[NB];
__device__ int   g_count;        // zero-init; last block resets it -> graph-replayable

__device__ __forceinline__ u64 pack2(float lo, float hi) {
    u64 r; asm("mov.b64 %0,{%1,%2};" : "=l"(r) : "f"(lo), "f"(hi)); return r;
}
__device__ __forceinline__ void unpack2(u64 v, float& lo, float& hi) {
    asm("mov.b64 {%0,%1},%2;" : "=f"(lo), "=f"(hi) : "l"(v));
}
// packed dual-fp32 FMA (Blackwell f32x2 pipe; 2 MACs per issue slot)
__device__ __forceinline__ u64 fma2(u64 a, u64 b, u64 c) {
    u64 d; asm("fma.rn.f32x2 %0,%1,%2,%3;" : "=l"(d) : "l"(a), "l"(b), "l"(c)); return d;
}

__global__ __launch_bounds__(256, 4)
void vq_main(const float* __restrict__ lat,
             const float* __restrict__ cb,
             const float* __restrict__ lpmf,
             float* __restrict__ out)
{
    // Packed codebook: pair p -> {-2*c[2p][d], -2*c[2p+1][d]} split for LDS.128 loads
    __shared__ ulonglong2 s_n01[NPAIR];   // {n_d0, n_d1}
    __shared__ ulonglong2 s_n23[NPAIR];   // {n_d2, n_d3}
    __shared__ u64        s_bias[NPAIR];
    __shared__ float4     s_cw[KCODE];
    __shared__ float      s_l2p[KCODE];
    __shared__ float      s_ind[CHUNKS_PER_B];
    __shared__ float      s_rm[8];
    __shared__ float      s_rr[8];
    __shared__ int        s_last;

    const int tid = threadIdx.x;
    const int b   = blockIdx.x;

    // ---- codebook prep (tiny; stays hot in L2 across blocks) ----
    {
        float4 ck = *(const float4*)(cb + tid * 4);
        s_cw[tid]  = ck;
        s_l2p[tid] = lpmf[tid] * NEG_INV_LN2;
    }
    if (tid < NPAIR) {
        const int p = tid;
        float4 c0 = *(const float4*)(cb + (2 * p) * 4);
        float4 c1 = *(const float4*)(cb + (2 * p + 1) * 4);
        ulonglong2 a, bq;
        a.x  = pack2(-2.f * c0.x, -2.f * c1.x);
        a.y  = pack2(-2.f * c0.y, -2.f * c1.y);
        bq.x = pack2(-2.f * c0.z, -2.f * c1.z);
        bq.y = pack2(-2.f * c0.w, -2.f * c1.w);
        s_n01[p] = a;
        s_n23[p] = bq;
        float b0 = c0.x*c0.x + c0.y*c0.y + c0.z*c0.z + c0.w*c0.w
                 + lpmf[2*p]     * NEG_INV_LN2 * INV_LMBDA;
        float b1 = c1.x*c1.x + c1.y*c1.y + c1.z*c1.z + c1.w*c1.w
                 + lpmf[2*p + 1] * NEG_INV_LN2 * INV_LMBDA;
        s_bias[p] = pack2(b0, b1);
    }
    __syncthreads();

    // ---- thread -> 4 chunks (c, w0..w0+3) of block b ----
    const int w0 = (tid & 15) * 4;     // 16 w-groups of 4
    const int c  = tid >> 4;           // 0..15 chunk row-group

    const int h0 = 4 * c, h1 = h0 + 1, h2 = h0 + 2, h3 = h0 + 3;
    const int s2 = (h2 < HH) ? h2 : h2 - 2;   // c==15: 62 -> 60
    const int s3 = (h3 < HH) ? h3 : h3 - 2;   // c==15: 63 -> 61

    const float* base = lat + (size_t)b * (HH * WW) + w0;
    float4 v0 = *(const float4*)(base + h0 * WW);
    float4 v1 = *(const float4*)(base + h1 * WW);
    float4 v2 = *(const float4*)(base + s2 * WW);
    float4 v3 = *(const float4*)(base + s3 * WW);

    const float* f0 = (const float*)&v0;
    const float* f1 = (const float*)&v1;
    const float* f2 = (const float*)&v2;
    const float* f3 = (const float*)&v3;

    // chunk j (w = w0+j) has elements (f0[j], f1[j], f2[j], f3[j]); pack duplicated
    u64 xq0[4], xq1[4], xq2[4], xq3[4];
    #pragma unroll
    for (int j = 0; j < 4; ++j) {
        xq0[j] = pack2(f0[j], f0[j]);
        xq1[j] = pack2(f1[j], f1[j]);
        xq2[j] = pack2(f2[j], f2[j]);
        xq3[j] = pack2(f3[j], f3[j]);
    }

    // ---- main loop: value-only min over 32 groups of 8 codewords ----
    // score_k = (||c_k||^2 + log2_pmf_k/lambda) - 2 * <x, c_k>
    float best[4] = {3.4e38f, 3.4e38f, 3.4e38f, 3.4e38f};
    int   bgrp[4] = {0, 0, 0, 0};

    #pragma unroll 1
    for (int g = 0; g < 32; ++g) {
        float pm[4][4];
        #pragma unroll
        for (int q = 0; q < 4; ++q) {
            const int p = (g << 2) + q;
            ulonglong2 n01 = s_n01[p];
            ulonglong2 n23 = s_n23[p];
            u64 bias = s_bias[p];
            #pragma unroll
            for (int j = 0; j < 4; ++j) {
                u64 a = fma2(xq0[j], n01.x, bias);
                a = fma2(xq1[j], n01.y, a);
                a = fma2(xq2[j], n23.x, a);
                a = fma2(xq3[j], n23.y, a);
                float lo, hi; unpack2(a, lo, hi);
                pm[j][q] = fminf(lo, hi);
            }
        }
        #pragma unroll
        for (int j = 0; j < 4; ++j) {
            float gm = fminf(fminf(pm[j][0], pm[j][1]), fminf(pm[j][2], pm[j][3]));
            // strict < keeps the earliest group on ties (first-index-wins)
            if (gm < best[j]) { best[j] = gm; bgrp[j] = g; }
        }
    }

    // ---- index recovery: recompute the winning group's 8 scores bit-exactly,
    //      descending overwrite-on-equality -> lowest k wins (jnp.argmin ties) ----
    int bi[4];
    #pragma unroll
    for (int j = 0; j < 4; ++j) {
        int idx = 0;
        const int pbase = bgrp[j] << 2;
        #pragma unroll
        for (int q = 3; q >= 0; --q) {
            const int p = pbase + q;
            ulonglong2 n01 = s_n01[p];
            ulonglong2 n23 = s_n23[p];
            u64 bias = s_bias[p];
            u64 a = fma2(xq0[j], n01.x, bias);
            a = fma2(xq1[j], n01.y, a);
            a = fma2(xq2[j], n23.x, a);
            a = fma2(xq3[j], n23.y, a);
            float lo, hi; unpack2(a, lo, hi);
            if (hi == best[j]) idx = 2 * p + 1;
            if (lo == best[j]) idx = 2 * p;
        }
        bi[j] = idx;
    }

    // ---- gather chosen codewords ----
    float4 q0 = s_cw[bi[0]];
    float4 q1 = s_cw[bi[1]];
    float4 q2 = s_cw[bi[2]];
    float4 q3 = s_cw[bi[3]];

    // ql writes: row d at (h_d, w0..w0+3) = (q0[d], q1[d], q2[d], q3[d]) -> STG.128
    float* oql = out + (size_t)b * (HH * WW) + w0;
    {
        float4 r0 = make_float4(q0.x, q1.x, q2.x, q3.x);
        float4 r1 = make_float4(q0.y, q1.y, q2.y, q3.y);
        *(float4*)(oql + h0 * WW) = r0;
        *(float4*)(oql + h1 * WW) = r1;
        if (h2 < HH) {
            float4 r2 = make_float4(q0.z, q1.z, q2.z, q3.z);
            *(float4*)(oql + h2 * WW) = r2;
        }
        if (h3 < HH) {
            float4 r3 = make_float4(q0.w, q1.w, q2.w, q3.w);
            *(float4*)(oql + h3 * WW) = r3;
        }
    }

    // mse / rate partials (all 16 elements count, incl. padded duplicates)
    float lm, lr;
    {
        float d00 = q0.x - f0[0], d01 = q0.y - f1[0], d02 = q0.z - f2[0], d03 = q0.w - f3[0];
        float d10 = q1.x - f0[1], d11 = q1.y - f1[1], d12 = q1.z - f2[1], d13 = q1.w - f3[1];
        float d20 = q2.x - f0[2], d21 = q2.y - f1[2], d22 = q2.z - f2[2], d23 = q2.w - f3[2];
        float d30 = q3.x - f0[3], d31 = q3.y - f1[3], d32 = q3.z - f2[3], d33 = q3.w - f3[3];
        lm = d00*d00 + d01*d01 + d02*d02 + d03*d03
           + d10*d10 + d11*d11 + d12*d12 + d13*d13
           + d20*d20 + d21*d21 + d22*d22 + d23*d23
           + d30*d30 + d31*d31 + d32*d32 + d33*d33;
        lr = s_l2p[bi[0]] + s_l2p[bi[1]] + s_l2p[bi[2]] + s_l2p[bi[3]];
    }

    // inds: flat order m = b*1024 + w*16 + c  (SMEM transpose -> coalesced stores)
    s_ind[(w0 + 0) * 16 + c] = (float)bi[0];
    s_ind[(w0 + 1) * 16 + c] = (float)bi[1];
    s_ind[(w0 + 2) * 16 + c] = (float)bi[2];
    s_ind[(w0 + 3) * 16 + c] = (float)bi[3];

    // ---- deterministic block reduction ----
    #pragma unroll
    for (int o = 16; o > 0; o >>= 1) {
        lm += __shfl_down_sync(0xFFFFFFFFu, lm, o);
        lr += __shfl_down_sync(0xFFFFFFFFu, lr, o);
    }
    if ((tid & 31) == 0) { s_rm[tid >> 5] = lm; s_rr[tid >> 5] = lr; }
    __syncthreads();

    // coalesced inds writeout
    float* oind = out + OFF_INDS + (size_t)b * CHUNKS_PER_B;
    oind[tid]       = s_ind[tid];
    oind[tid + 256] = s_ind[tid + 256];
    oind[tid + 512] = s_ind[tid + 512];
    oind[tid + 768] = s_ind[tid + 768];

    if (tid == 0) {
        float sm_ = 0.f, sr_ = 0.f;
        #pragma unroll
        for (int i = 0; i < 8; ++i) { sm_ += s_rm[i]; sr_ += s_rr[i]; }
        g_pmse[b]  = sm_;
        g_prate[b] = sr_;
        __threadfence();
        int v = atomicAdd(&g_count, 1);
        s_last = (v == NB - 1);
    }
    __syncthreads();

    // ---- fused finalize: last block reduces the 768 partials (fixed order) ----
    if (s_last) {
        __threadfence();   // acquire: make all blocks' partials visible
        float a = g_pmse[tid] + g_pmse[tid + 256] + g_pmse[tid + 512];
        float r = g_prate[tid] + g_prate[tid + 256] + g_prate[tid + 512];
        s_ind[tid]       = a;          // reuse smem
        s_ind[tid + 256] = r;
        __syncthreads();
        #pragma unroll
        for (int s = 128; s > 0; s >>= 1) {
            if (tid < s) {
                s_ind[tid]       += s_ind[tid + s];
                s_ind[256 + tid] += s_ind[256 + tid + s];
            }
            __syncthreads();
        }
        if (tid == 0) {
            out[OFF_MSE]   = s_ind[0] * (1.0f / MSE_COUNT);
            out[OFF_RATE]  = s_ind[256];
            out[OFF_PRIOR] = 0.f;
            out[OFF_PARAM] = 0.f;
            g_count = 0;   // reset for next graph replay
        }
    }
}

extern "C" void kernel_launch(void* const* d_in, const int* in_sizes, int n_in,
                              void* d_out, int out_size)
{
    const float* lat  = (const float*)d_in[0];   // latents  (4,192,62,64)
    const float* cb   = (const float*)d_in[1];   // codebook (256,4)
    const float* lpmf = (const float*)d_in[2];   // log_pmf  (256,)
    float* out = (float*)d_out;

    vq_main<<<NB, 256>>>(lat, cb, lpmf, out);
}

// round 6
// speedup vs baseline: 1.4979x; 1.0449x over previous
#include <cuda_runtime.h>

// Problem constants
#define NB      768          // N*C
#define NB4     3072         // quarter-blocks
#define HH      62
#define WW      64
#define KCODE   256
#define NPAIR   128
#define CHUNKS_PER_B 1024    // W * Hp / D
#define M_TOTAL (NB * CHUNKS_PER_B)          // 786432
#define QL_ELEMS (NB * HH * WW)              // 3047424
#define OFF_MSE   QL_ELEMS
#define OFF_INDS  (QL_ELEMS + 1)
#define OFF_RATE  (OFF_INDS + M_TOTAL)
#define OFF_PRIOR (OFF_RATE + 1)
#define OFF_PARAM (OFF_RATE + 2)
#define MSE_COUNT 3145728.0f                 // NB * 1024 * 4

#define NEG_INV_LN2 (-1.4426950408889634f)
#define INV_LMBDA   100.0f

typedef unsigned long long u64;

// Deterministic per-(quarter)block partials + completion counter
__device__ float g_pmse[NB4];
__device__ float g_prate[NB4];
__device__ int   g_count;        // zero-init; last block resets it -> graph-replayable

__device__ __forceinline__ u64 pack2(float lo, float hi) {
    u64 r; asm("mov.b64 %0,{%1,%2};" : "=l"(r) : "f"(lo), "f"(hi)); return r;
}
__device__ __forceinline__ void unpack2(u64 v, float& lo, float& hi) {
    asm("mov.b64 {%0,%1},%2;" : "=f"(lo), "=f"(hi) : "l"(v));
}
// packed dual-fp32 FMA (Blackwell f32x2 pipe; 2 MACs per issue slot)
__device__ __forceinline__ u64 fma2(u64 a, u64 b, u64 c) {
    u64 d; asm("fma.rn.f32x2 %0,%1,%2,%3;" : "=l"(d) : "l"(a), "l"(b), "l"(c)); return d;
}

__global__ __launch_bounds__(64)
void vq_main(const float* __restrict__ lat,
             const float* __restrict__ cb,
             const float* __restrict__ lpmf,
             float* __restrict__ out)
{
    // Packed codebook: pair p -> {-2*c[2p][d], -2*c[2p+1][d]} split for LDS.128 loads
    __shared__ ulonglong2 s_n01[NPAIR];   // {n_d0, n_d1}
    __shared__ ulonglong2 s_n23[NPAIR];   // {n_d2, n_d3}
    __shared__ u64        s_bias[NPAIR];
    __shared__ float4     s_cw[KCODE];
    __shared__ float      s_l2p[KCODE];
    __shared__ float      s_ind[256];     // this quarter's 256 chunk indices
    __shared__ float      s_rm[2];
    __shared__ float      s_rr[2];
    __shared__ int        s_last;

    const int tid = threadIdx.x;         // 0..63
    const int blk = blockIdx.x;          // 0..3071
    const int b   = blk >> 2;            // 0..767
    const int wq  = blk & 3;             // quarter: w in [wq*16, wq*16+16)

    // ---- codebook prep (tiny; stays hot in L2 across blocks) ----
    #pragma unroll
    for (int i = 0; i < 4; ++i) {
        const int k = tid * 4 + i;
        float4 ck = *(const float4*)(cb + k * 4);
        s_cw[k]  = ck;
        s_l2p[k] = lpmf[k] * NEG_INV_LN2;
    }
    #pragma unroll
    for (int i = 0; i < 2; ++i) {
        const int p = tid * 2 + i;
        float4 c0 = *(const float4*)(cb + (2 * p) * 4);
        float4 c1 = *(const float4*)(cb + (2 * p + 1) * 4);
        ulonglong2 a, bq;
        a.x  = pack2(-2.f * c0.x, -2.f * c1.x);
        a.y  = pack2(-2.f * c0.y, -2.f * c1.y);
        bq.x = pack2(-2.f * c0.z, -2.f * c1.z);
        bq.y = pack2(-2.f * c0.w, -2.f * c1.w);
        s_n01[p] = a;
        s_n23[p] = bq;
        float b0 = c0.x*c0.x + c0.y*c0.y + c0.z*c0.z + c0.w*c0.w
                 + lpmf[2*p]     * NEG_INV_LN2 * INV_LMBDA;
        float b1 = c1.x*c1.x + c1.y*c1.y + c1.z*c1.z + c1.w*c1.w
                 + lpmf[2*p + 1] * NEG_INV_LN2 * INV_LMBDA;
        s_bias[p] = pack2(b0, b1);
    }
    __syncthreads();

    // ---- thread -> 4 chunks (c, w0..w0+3) ----
    const int wl = (tid & 3) * 4;        // local w group of 4 within this quarter
    const int w0 = wq * 16 + wl;         // global w
    const int c  = tid >> 2;             // 0..15 chunk row-group

    const int h0 = 4 * c, h1 = h0 + 1, h2 = h0 + 2, h3 = h0 + 3;
    const int s2 = (h2 < HH) ? h2 : h2 - 2;   // c==15: 62 -> 60
    const int s3 = (h3 < HH) ? h3 : h3 - 2;   // c==15: 63 -> 61

    const float* base = lat + (size_t)b * (HH * WW) + w0;
    float4 v0 = *(const float4*)(base + h0 * WW);
    float4 v1 = *(const float4*)(base + h1 * WW);
    float4 v2 = *(const float4*)(base + s2 * WW);
    float4 v3 = *(const float4*)(base + s3 * WW);

    const float* f0 = (const float*)&v0;
    const float* f1 = (const float*)&v1;
    const float* f2 = (const float*)&v2;
    const float* f3 = (const float*)&v3;

    // chunk j (w = w0+j) has elements (f0[j], f1[j], f2[j], f3[j]); pack duplicated
    u64 xq0[4], xq1[4], xq2[4], xq3[4];
    #pragma unroll
    for (int j = 0; j < 4; ++j) {
        xq0[j] = pack2(f0[j], f0[j]);
        xq1[j] = pack2(f1[j], f1[j]);
        xq2[j] = pack2(f2[j], f2[j]);
        xq3[j] = pack2(f3[j], f3[j]);
    }

    // ---- main loop: value-only min over 32 groups of 8 codewords ----
    // score_k = (||c_k||^2 + log2_pmf_k/lambda) - 2 * <x, c_k>
    float best[4] = {3.4e38f, 3.4e38f, 3.4e38f, 3.4e38f};
    int   bgrp[4] = {0, 0, 0, 0};

    #pragma unroll 2
    for (int g = 0; g < 32; ++g) {
        float pm[4][4];
        #pragma unroll
        for (int q = 0; q < 4; ++q) {
            const int p = (g << 2) + q;
            ulonglong2 n01 = s_n01[p];
            ulonglong2 n23 = s_n23[p];
            u64 bias = s_bias[p];
            #pragma unroll
            for (int j = 0; j < 4; ++j) {
                u64 a = fma2(xq0[j], n01.x, bias);
                a = fma2(xq1[j], n01.y, a);
                a = fma2(xq2[j], n23.x, a);
                a = fma2(xq3[j], n23.y, a);
                float lo, hi; unpack2(a, lo, hi);
                pm[j][q] = fminf(lo, hi);
            }
        }
        #pragma unroll
        for (int j = 0; j < 4; ++j) {
            float gm = fminf(fminf(pm[j][0], pm[j][1]), fminf(pm[j][2], pm[j][3]));
            // strict < keeps the earliest group on ties (first-index-wins)
            if (gm < best[j]) { best[j] = gm; bgrp[j] = g; }
        }
    }

    // ---- index recovery: recompute the winning group's 8 scores bit-exactly,
    //      descending overwrite-on-equality -> lowest k wins (jnp.argmin ties) ----
    int bi[4];
    #pragma unroll
    for (int j = 0; j < 4; ++j) {
        int idx = 0;
        const int pbase = bgrp[j] << 2;
        #pragma unroll
        for (int q = 3; q >= 0; --q) {
            const int p = pbase + q;
            ulonglong2 n01 = s_n01[p];
            ulonglong2 n23 = s_n23[p];
            u64 bias = s_bias[p];
            u64 a = fma2(xq0[j], n01.x, bias);
            a = fma2(xq1[j], n01.y, a);
            a = fma2(xq2[j], n23.x, a);
            a = fma2(xq3[j], n23.y, a);
            float lo, hi; unpack2(a, lo, hi);
            if (hi == best[j]) idx = 2 * p + 1;
            if (lo == best[j]) idx = 2 * p;
        }
        bi[j] = idx;
    }

    // ---- gather chosen codewords ----
    float4 q0 = s_cw[bi[0]];
    float4 q1 = s_cw[bi[1]];
    float4 q2 = s_cw[bi[2]];
    float4 q3 = s_cw[bi[3]];

    // ql writes: row d at (h_d, w0..w0+3) = (q0[d], q1[d], q2[d], q3[d]) -> STG.128
    float* oql = out + (size_t)b * (HH * WW) + w0;
    {
        float4 r0 = make_float4(q0.x, q1.x, q2.x, q3.x);
        float4 r1 = make_float4(q0.y, q1.y, q2.y, q3.y);
        *(float4*)(oql + h0 * WW) = r0;
        *(float4*)(oql + h1 * WW) = r1;
        if (h2 < HH) {
            float4 r2 = make_float4(q0.z, q1.z, q2.z, q3.z);
            *(float4*)(oql + h2 * WW) = r2;
        }
        if (h3 < HH) {
            float4 r3 = make_float4(q0.w, q1.w, q2.w, q3.w);
            *(float4*)(oql + h3 * WW) = r3;
        }
    }

    // mse / rate partials (all 16 elements count, incl. padded duplicates)
    float lm, lr;
    {
        float d00 = q0.x - f0[0], d01 = q0.y - f1[0], d02 = q0.z - f2[0], d03 = q0.w - f3[0];
        float d10 = q1.x - f0[1], d11 = q1.y - f1[1], d12 = q1.z - f2[1], d13 = q1.w - f3[1];
        float d20 = q2.x - f0[2], d21 = q2.y - f1[2], d22 = q2.z - f2[2], d23 = q2.w - f3[2];
        float d30 = q3.x - f0[3], d31 = q3.y - f1[3], d32 = q3.z - f2[3], d33 = q3.w - f3[3];
        lm = d00*d00 + d01*d01 + d02*d02 + d03*d03
           + d10*d10 + d11*d11 + d12*d12 + d13*d13
           + d20*d20 + d21*d21 + d22*d22 + d23*d23
           + d30*d30 + d31*d31 + d32*d32 + d33*d33;
        lr = s_l2p[bi[0]] + s_l2p[bi[1]] + s_l2p[bi[2]] + s_l2p[bi[3]];
    }

    // inds: flat m = b*1024 + w*16 + c; this quarter owns [b*1024 + wq*256, +256)
    s_ind[(wl + 0) * 16 + c] = (float)bi[0];
    s_ind[(wl + 1) * 16 + c] = (float)bi[1];
    s_ind[(wl + 2) * 16 + c] = (float)bi[2];
    s_ind[(wl + 3) * 16 + c] = (float)bi[3];

    // ---- deterministic block reduction (2 warps) ----
    #pragma unroll
    for (int o = 16; o > 0; o >>= 1) {
        lm += __shfl_down_sync(0xFFFFFFFFu, lm, o);
        lr += __shfl_down_sync(0xFFFFFFFFu, lr, o);
    }
    if ((tid & 31) == 0) { s_rm[tid >> 5] = lm; s_rr[tid >> 5] = lr; }
    __syncthreads();

    // coalesced inds writeout (256 floats by 64 threads)
    float* oind = out + OFF_INDS + (size_t)b * CHUNKS_PER_B + wq * 256;
    oind[tid]       = s_ind[tid];
    oind[tid + 64]  = s_ind[tid + 64];
    oind[tid + 128] = s_ind[tid + 128];
    oind[tid + 192] = s_ind[tid + 192];

    if (tid == 0) {
        g_pmse[blk]  = s_rm[0] + s_rm[1];
        g_prate[blk] = s_rr[0] + s_rr[1];
        __threadfence();
        int v = atomicAdd(&g_count, 1);
        s_last = (v == NB4 - 1);
    }
    __syncthreads();

    // ---- fused finalize: last block reduces the 3072 partials (fixed order) ----
    if (s_last) {
        __threadfence();   // acquire: make all blocks' partials visible
        float a = 0.f, r = 0.f;
        #pragma unroll
        for (int i = 0; i < 48; ++i) {      // 3072 = 64*48, fixed order
            a += g_pmse[tid + i * 64];
            r += g_prate[tid + i * 64];
        }
        s_ind[tid]      = a;                // reuse smem
        s_ind[tid + 64] = r;
        __syncthreads();
        #pragma unroll
        for (int s = 32; s > 0; s >>= 1) {
            if (tid < s) {
                s_ind[tid]      += s_ind[tid + s];
                s_ind[64 + tid] += s_ind[64 + tid + s];
            }
            __syncthreads();
        }
        if (tid == 0) {
            out[OFF_MSE]   = s_ind[0] * (1.0f / MSE_COUNT);
            out[OFF_RATE]  = s_ind[64];
            out[OFF_PRIOR] = 0.f;
            out[OFF_PARAM] = 0.f;
            g_count = 0;   // reset for next graph replay
        }
    }
}

extern "C" void kernel_launch(void* const* d_in, const int* in_sizes, int n_in,
                              void* d_out, int out_size)
{
    const float* lat  = (const float*)d_in[0];   // latents  (4,192,62,64)
    const float* cb   = (const float*)d_in[1];   // codebook (256,4)
    const float* lpmf = (const float*)d_in[2];   // log_pmf  (256,)
    float* out = (float*)d_out;

    vq_main<<<NB4, 64>>>(lat, cb, lpmf, out);
}